// round 7
// baseline (speedup 1.0000x reference)
#include <cuda_runtime.h>
#include <math.h>

#define BATCH 128
#define SEQ 48
#define FEAT 60
#define NH 5
#define NV 6
#define TWO_PI 6.2831853071795864769f

struct C2 { float re, im; };
struct M2 { C2 m00, m01, m10, m11; };

__device__ __forceinline__ C2 cmul(C2 a, C2 b) {
    C2 r; r.re = a.re*b.re - a.im*b.im; r.im = a.re*b.im + a.im*b.re; return r;
}
__device__ __forceinline__ C2 cadd(C2 a, C2 b) { C2 r{a.re+b.re, a.im+b.im}; return r; }

// U = RZ(t3) * RY(t2) * RX(t1)  (precise sincosf: runs once)
__device__ __forceinline__ M2 fuse_zyx(float t1, float t2, float t3) {
    float c1,s1,c2,s2,c3,s3;
    sincosf(0.5f*t1, &s1, &c1);
    sincosf(0.5f*t2, &s2, &c2);
    sincosf(0.5f*t3, &s3, &c3);
    C2 a00{c1,0.f}, a01{0.f,-s1}, a10{0.f,-s1}, a11{c1,0.f};
    C2 m00{c2*a00.re - s2*a10.re, c2*a00.im - s2*a10.im};
    C2 m01{c2*a01.re - s2*a11.re, c2*a01.im - s2*a11.im};
    C2 m10{s2*a00.re + c2*a10.re, s2*a00.im + c2*a10.im};
    C2 m11{s2*a01.re + c2*a11.re, s2*a01.im + c2*a11.im};
    C2 r0{c3,-s3}, r1{c3,s3};
    M2 u;
    u.m00 = cmul(r0,m00); u.m01 = cmul(r0,m01);
    u.m10 = cmul(r1,m10); u.m11 = cmul(r1,m11);
    return u;
}
__device__ __forceinline__ M2 mmul(M2 p, M2 q) {
    M2 r;
    r.m00 = cadd(cmul(p.m00,q.m00), cmul(p.m01,q.m10));
    r.m01 = cadd(cmul(p.m00,q.m01), cmul(p.m01,q.m11));
    r.m10 = cadd(cmul(p.m10,q.m00), cmul(p.m11,q.m10));
    r.m11 = cadd(cmul(p.m10,q.m01), cmul(p.m11,q.m11));
    return r;
}

template<int M>
__device__ __forceinline__ void g1q(float* Sr, float* Si, M2 g) {
    #pragma unroll
    for (int i = 0; i < 32; ++i) {
        if ((i & M) == 0) {
            const int j = i | M;
            float ar = Sr[i], ai = Si[i], br = Sr[j], bi = Si[j];
            Sr[i] = g.m00.re*ar - g.m00.im*ai + g.m01.re*br - g.m01.im*bi;
            Si[i] = g.m00.re*ai + g.m00.im*ar + g.m01.re*bi + g.m01.im*br;
            Sr[j] = g.m10.re*ar - g.m10.im*ai + g.m11.re*br - g.m11.im*bi;
            Si[j] = g.m10.re*ai + g.m10.im*ar + g.m11.re*bi + g.m11.im*br;
        }
    }
}
template<int MC, int MT>
__device__ __forceinline__ void gcrx(float* Sr, float* Si, float c, float s) {
    #pragma unroll
    for (int i = 0; i < 32; ++i) {
        if ((i & MC) != 0 && (i & MT) == 0) {
            const int j = i | MT;
            float a0r = Sr[i], a0i = Si[i], a1r = Sr[j], a1i = Si[j];
            Sr[i] = c*a0r + s*a1i;
            Si[i] = c*a0i - s*a1r;
            Sr[j] = s*a0i + c*a1r;
            Si[j] = c*a1i - s*a0r;
        }
    }
}

__device__ __forceinline__ unsigned long long pack2(float lo, float hi) {
    unsigned long long r;
    asm("mov.b64 %0, {%1, %2};" : "=l"(r) : "r"(__float_as_uint(lo)), "r"(__float_as_uint(hi)));
    return r;
}
__device__ __forceinline__ void unpack2(unsigned long long v, float& lo, float& hi) {
    unsigned a, b;
    asm("mov.b64 {%0, %1}, %2;" : "=r"(a), "=r"(b) : "l"(v));
    lo = __uint_as_float(a); hi = __uint_as_float(b);
}
__device__ __forceinline__ void fma2(unsigned long long& acc, unsigned long long a, unsigned long long b) {
    asm("fma.rn.f32x2 %0, %1, %2, %0;" : "+l"(acc) : "l"(a), "l"(b));
}
__device__ __forceinline__ unsigned long long mul2(unsigned long long a, unsigned long long b) {
    unsigned long long r;
    asm("mul.rn.f32x2 %0, %1, %2;" : "=l"(r) : "l"(a), "l"(b));
    return r;
}

__global__ __launch_bounds__(128)
void qrnn_kernel(const float* __restrict__ x,
                 const float* __restrict__ hidden,
                 const float* __restrict__ params,
                 float* __restrict__ out)
{
    const int b = blockIdx.x;
    __shared__ float Tre[32][33];
    __shared__ float Tim[32][33];

    if (threadIdx.x < 32) {
        // ================= warp 0: hidden recurrence (5-qubit sim) =================
        const int lane = threadIdx.x;

        // z_q lives on lane 1<<(4-q)
        const bool special = (__popc(lane) == 1) && (lane <= 16);
        const int q_of_lane = special ? (__clz(lane) - 27) : 0;   // lane16->q0 ... lane1->q4

        // ---- precompute U'' = CRX1 * G2 * CRX0 * G1 * Phase  (column per lane) ----
        unsigned long long PRr[16], PRi[16];
        {
            M2 h1[5], h2[5];
            #pragma unroll
            for (int q = 0; q < 5; q++) {
                h1[q] = fuse_zyx(params[3*q],    params[3*q+1],    params[3*q+2]);
                h2[q] = fuse_zyx(params[37+3*q], params[37+3*q+1], params[37+3*q+2]);
            }
            float cx[8], sx[8];
            #pragma unroll
            for (int k = 0; k < 8; k++) {
                int l = k >> 2, kk = k & 3;
                sincosf(0.5f*params[l*37 + 15 + kk], &sx[k], &cx[k]);
            }

            float Sr[32], Si[32];
            #pragma unroll
            for (int i = 0; i < 32; ++i) { Sr[i] = (i == lane) ? 1.f : 0.f; Si[i] = 0.f; }

            // layer-0 1q gates (folded in)
            g1q<16>(Sr, Si, h1[0]);
            g1q< 8>(Sr, Si, h1[1]);
            g1q< 4>(Sr, Si, h1[2]);
            g1q< 2>(Sr, Si, h1[3]);
            g1q< 1>(Sr, Si, h1[4]);
            // layer-0 CRX chain
            gcrx<16,8>(Sr, Si, cx[0], sx[0]);
            gcrx< 8,4>(Sr, Si, cx[1], sx[1]);
            gcrx< 4,2>(Sr, Si, cx[2], sx[2]);
            gcrx< 2,1>(Sr, Si, cx[3], sx[3]);
            // layer-1 1q gates
            g1q<16>(Sr, Si, h2[0]);
            g1q< 8>(Sr, Si, h2[1]);
            g1q< 4>(Sr, Si, h2[2]);
            g1q< 2>(Sr, Si, h2[3]);
            g1q< 1>(Sr, Si, h2[4]);
            // layer-1 CRX chain
            gcrx<16,8>(Sr, Si, cx[4], sx[4]);
            gcrx< 8,4>(Sr, Si, cx[5], sx[5]);
            gcrx< 4,2>(Sr, Si, cx[6], sx[6]);
            gcrx< 2,1>(Sr, Si, cx[7], sx[7]);

            // fold embed phase (-i)^popc(column) into this column
            {
                int k = __popc(lane) & 3;
                #pragma unroll
                for (int i = 0; i < 32; ++i) {
                    float r = Sr[i], im = Si[i];
                    if (k == 1)      { Sr[i] =  im; Si[i] = -r;  }
                    else if (k == 2) { Sr[i] = -r;  Si[i] = -im; }
                    else if (k == 3) { Sr[i] = -im; Si[i] =  r;  }
                }
            }

            // transpose via padded SMEM: lane i ends with ROW i, packed in col pairs
            #pragma unroll
            for (int i = 0; i < 32; ++i) { Tre[i][lane] = Sr[i]; Tim[i][lane] = Si[i]; }
            __syncwarp();
            #pragma unroll
            for (int j2 = 0; j2 < 16; ++j2) {
                PRr[j2] = pack2(Tre[lane][2*j2], Tre[lane][2*j2+1]);
                PRi[j2] = pack2(Tim[lane][2*j2], Tim[lane][2*j2+1]);
            }
        }

        float z = special ? hidden[b*NH + q_of_lane] : 0.f;

        #pragma unroll 1
        for (int t = 0; t < SEQ; ++t) {
            // ---- sincos on special lanes; broadcast 5 (cc,ss) pairs ----
            float cc, ss;
            __sincosf(0.5f*z, &ss, &cc);
            float c0 = __shfl_sync(0xffffffffu, cc, 16);
            float s0 = __shfl_sync(0xffffffffu, ss, 16);
            float c1 = __shfl_sync(0xffffffffu, cc, 8);
            float s1 = __shfl_sync(0xffffffffu, ss, 8);
            float c2 = __shfl_sync(0xffffffffu, cc, 4);
            float s2 = __shfl_sync(0xffffffffu, ss, 4);
            float c3 = __shfl_sync(0xffffffffu, cc, 2);
            float s3 = __shfl_sync(0xffffffffu, ss, 2);
            float c4 = __shfl_sync(0xffffffffu, cc, 1);
            float s4 = __shfl_sync(0xffffffffu, ss, 1);

            // ---- local subset-product tree over qubits 0..3 (16 bases) ----
            // base[j]: bit3=q0, bit2=q1, bit1=q2, bit0=q3
            float t1a[4];
            t1a[0] = c0*c1; t1a[1] = c0*s1; t1a[2] = s0*c1; t1a[3] = s0*s1;
            float t2a[8];
            #pragma unroll
            for (int k = 0; k < 4; ++k) { t2a[2*k] = t1a[k]*c2; t2a[2*k+1] = t1a[k]*s2; }
            float base[16];
            #pragma unroll
            for (int k = 0; k < 8; ++k) { base[2*k] = t2a[k]*c3; base[2*k+1] = t2a[k]*s3; }

            const unsigned long long cs4 = pack2(c4, s4);

            // ---- matvec amp' = U'' * m : m pair = (base_j*c4, base_j*s4) ----
            unsigned long long aR0=0ull, aR1=0ull, aI0=0ull, aI1=0ull;
            #pragma unroll
            for (int j2 = 0; j2 < 16; j2 += 2) {
                unsigned long long mp0 = mul2(pack2(base[j2],   base[j2]),   cs4);
                unsigned long long mp1 = mul2(pack2(base[j2+1], base[j2+1]), cs4);
                fma2(aR0, PRr[j2],   mp0);
                fma2(aI0, PRi[j2],   mp0);
                fma2(aR1, PRr[j2+1], mp1);
                fma2(aI1, PRi[j2+1], mp1);
            }
            float x0,x1,y0,y1,u0,u1,v0,v1;
            unpack2(aR0, x0, x1); unpack2(aR1, y0, y1);
            unpack2(aI0, u0, u1); unpack2(aI1, v0, v1);
            float nar = (x0 + x1) + (y0 + y1);
            float nai = (u0 + u1) + (v0 + v1);

            // ---- measure: Walsh-Hadamard signed butterfly; lane 1<<(4-q) keeps z_q ----
            float v = fmaf(nar, nar, nai*nai);
            #pragma unroll
            for (int m2 = 16; m2 >= 1; m2 >>= 1) {
                float o = __shfl_xor_sync(0xffffffffu, v, m2);
                v = (lane & m2) ? (o - v) : (v + o);
            }
            z = special ? v : 0.f;
        }
        if (special) out[BATCH*SEQ*NV + b*NH + q_of_lane] = z;

    } else {
        // ============ warps 1-3: closed-form outputs for this batch ============
        const int t = threadIdx.x - 32;
        if (t >= SEQ) return;

        float Cc[6], Dd[6], Ee[6];
        #pragma unroll
        for (int q = 0; q < 6; q++) {
            M2 u0 = fuse_zyx(params[19+3*q],    params[20+3*q],    params[21+3*q]);
            M2 u1 = fuse_zyx(params[37+19+3*q], params[37+20+3*q], params[37+21+3*q]);
            M2 M = mmul(u1, u0);
            float h00 = (M.m00.re*M.m00.re + M.m00.im*M.m00.im)
                      - (M.m10.re*M.m10.re + M.m10.im*M.m10.im);
            float h11 = (M.m01.re*M.m01.re + M.m01.im*M.m01.im)
                      - (M.m11.re*M.m11.re + M.m11.im*M.m11.im);
            float imh01 = (M.m00.re*M.m01.im - M.m00.im*M.m01.re)
                        - (M.m10.re*M.m11.im - M.m10.im*M.m11.re);
            Cc[q] = 0.5f*(h00 + h11);
            Dd[q] = 0.5f*(h00 - h11);
            Ee[q] = imh01;
        }

        const int P = b * SEQ + t;
        const float4* x4 = (const float4*)(x + (size_t)P * FEAT);
        float vals[60];
        #pragma unroll
        for (int i = 0; i < 15; i++) {
            float4 v4 = x4[i];
            vals[4*i+0] = v4.x; vals[4*i+1] = v4.y;
            vals[4*i+2] = v4.z; vals[4*i+3] = v4.w;
        }
        float pooled[6];
        #pragma unroll
        for (int v = 0; v < 6; v++) {
            float s = 0.f;
            #pragma unroll
            for (int j = 0; j < 10; j++) s += vals[v*10 + j];
            pooled[v] = 0.1f * s;
        }
        float mn = pooled[0], mx = pooled[0];
        #pragma unroll
        for (int v = 1; v < 6; v++) {
            mn = fminf(mn, pooled[v]);
            mx = fmaxf(mx, pooled[v]);
        }
        float scale = TWO_PI / (mx - mn + 1e-8f);
        #pragma unroll
        for (int v = 0; v < 6; v++) {
            float a = scale * (pooled[v] - mn);
            float sa, ca;
            sincosf(a, &sa, &ca);
            out[(size_t)P*6 + v] = Cc[v] + Dd[v]*ca + Ee[v]*sa;
        }
    }
}

extern "C" void kernel_launch(void* const* d_in, const int* in_sizes, int n_in,
                              void* d_out, int out_size) {
    const float* x      = (const float*)d_in[0];
    const float* hidden = (const float*)d_in[1];
    const float* params = (const float*)d_in[2];
    float* out = (float*)d_out;
    qrnn_kernel<<<BATCH, 128>>>(x, hidden, params, out);
}